// round 1
// baseline (speedup 1.0000x reference)
#include <cuda_runtime.h>
#include <math.h>

#define TOT   65536
#define NB    64
#define NPG   1024
#define NE    2097152
#define INCH  128
#define HID   32
#define KC    16
#define OUTC  10

// ---------------- scratch (static device globals; no allocation) ----------------
__device__ float g_h  [TOT*HID];   // 8 MB : lin1 output
__device__ float g_agg[TOT*HID];   // 8 MB : A @ h
__device__ float g_h1 [TOT*HID];   // 8 MB : conv1 output
__device__ float g_s  [TOT*KC];    // 4 MB : softmax assignments
__device__ float g_as [TOT*KC];    // 4 MB : A @ s
__device__ float g_deg[TOT];       // out-degree per node
__device__ float g_out[NB*KC*HID]; // pooled features S^T H
__device__ float g_oa [NB*KC*KC];  // pooled adjacency S^T A S
__device__ float g_ss [NB*KC*KC];  // S^T S
__device__ float g_den[NB];        // tr(S^T D S)
__device__ float g_loss[2*NB];     // per-graph mincut / ortho

__device__ __forceinline__ void red4(float* p, float a, float b, float c, float d){
  asm volatile("red.global.add.v4.f32 [%0], {%1,%2,%3,%4};"
               :: "l"(p), "f"(a), "f"(b), "f"(c), "f"(d) : "memory");
}
__device__ __forceinline__ void red1(float* p, float a){
  asm volatile("red.global.add.f32 [%0], %1;" :: "l"(p), "f"(a) : "memory");
}

// ---------------- K1: h = x @ W1^T + b1 ; zero scratch ----------------
// grid 512 blocks x 256 threads; 128 rows/block; thread = 4 rows x 4 cols
__global__ void __launch_bounds__(256) k1(const float* __restrict__ x,
                                          const float* __restrict__ W1,
                                          const float* __restrict__ b1){
  __shared__ float sW[INCH*HID];   // sW[i*32+j] = W1[j*128+i]
  __shared__ float sb[HID];
  int tid = threadIdx.x;
  for (int u = tid; u < INCH*HID; u += 256){
    int i = u >> 5, j = u & 31;
    sW[u] = W1[j*INCH + i];
  }
  if (tid < HID) sb[tid] = b1[tid];

  // zero pooled scratch (grid covers it)
  int gid = blockIdx.x*256 + tid;
  if (gid < NB*KC*HID) g_out[gid] = 0.f;
  if (gid < NB*KC*KC){ g_oa[gid] = 0.f; g_ss[gid] = 0.f; }
  if (gid < NB) g_den[gid] = 0.f;

  // zero agg + deg for this block's rows
  int base = blockIdx.x * 128;
  float4 z4 = make_float4(0.f,0.f,0.f,0.f);
  float4* agg4 = reinterpret_cast<float4*>(g_agg) + base*8;
  for (int u = tid; u < 1024; u += 256) agg4[u] = z4;
  if (tid < 128) g_deg[base + tid] = 0.f;
  __syncthreads();

  int rg = tid >> 3;           // 0..31 -> 4 rows each
  int cg = tid & 7;            // 0..7  -> 4 cols each
  int r0 = base + rg*4;

  float acc[4][4];
  #pragma unroll
  for (int k = 0; k < 4; k++)
    #pragma unroll
    for (int c = 0; c < 4; c++) acc[k][c] = sb[cg*4 + c];

  #pragma unroll 4
  for (int i4 = 0; i4 < 32; i4++){
    float4 xq[4];
    #pragma unroll
    for (int k = 0; k < 4; k++)
      xq[k] = __ldg(reinterpret_cast<const float4*>(x + (size_t)(r0+k)*INCH) + i4);
    #pragma unroll
    for (int ii = 0; ii < 4; ii++){
      int i = i4*4 + ii;
      float wv[4];
      #pragma unroll
      for (int c = 0; c < 4; c++) wv[c] = sW[i*32 + cg*4 + c];
      #pragma unroll
      for (int k = 0; k < 4; k++){
        float xs = (&xq[k].x)[ii];
        #pragma unroll
        for (int c = 0; c < 4; c++) acc[k][c] += xs * wv[c];
      }
    }
  }
  float4* h4 = reinterpret_cast<float4*>(g_h);
  #pragma unroll
  for (int k = 0; k < 4; k++)
    h4[(size_t)(r0+k)*8 + cg] = make_float4(acc[k][0],acc[k][1],acc[k][2],acc[k][3]);
}

// ---------------- K2: edge scatter: agg[src] += h[dst]; deg[src] += 1 ----------------
__global__ void k2(const int* __restrict__ ei){
  int e = blockIdx.x*blockDim.x + threadIdx.x;
  if (e >= NE) return;
  int src = __ldg(ei + e);
  int dst = __ldg(ei + NE + e);
  const float4* hv = reinterpret_cast<const float4*>(g_h) + (size_t)dst*8;
  float* ap = g_agg + (size_t)src*HID;
  #pragma unroll
  for (int i = 0; i < 8; i++){
    float4 v = __ldg(hv + i);
    red4(ap + i*4, v.x, v.y, v.z, v.w);
  }
  red1(g_deg + src, 1.f);
}

// ---------------- K3: h1 = agg@Wrel1^T + h@Wroot1^T + brel1; s = softmax(h1@Wp^T+bp) ----------------
// grid 128 x 256; 2 nodes per thread
__global__ void __launch_bounds__(256) k3(const float* __restrict__ Wrel1,
                                          const float* __restrict__ brel1,
                                          const float* __restrict__ Wroot1,
                                          const float* __restrict__ Wp,
                                          const float* __restrict__ bp){
  __shared__ float sWr[HID*HID], sWo[HID*HID], sWp[HID*KC], sbr[HID], sbp[KC];
  int tid = threadIdx.x;
  for (int u = tid; u < HID*HID; u += 256){
    int i = u >> 5, j = u & 31;
    sWr[u] = Wrel1[j*HID + i];
    sWo[u] = Wroot1[j*HID + i];
  }
  for (int u = tid; u < HID*KC; u += 256){
    int i = u >> 4, j = u & 15;
    sWp[u] = Wp[j*HID + i];
  }
  if (tid < HID) sbr[tid] = brel1[tid];
  if (tid < KC)  sbp[tid] = bp[tid];
  __syncthreads();

  int n0 = blockIdx.x*512 + tid;
  int n1 = n0 + 256;

  float a0[HID], a1[HID];
  #pragma unroll
  for (int j = 0; j < HID; j++){ a0[j] = 0.f; a1[j] = 0.f; }

  const float4* ag4 = reinterpret_cast<const float4*>(g_agg);
  const float4* h4  = reinterpret_cast<const float4*>(g_h);
  #pragma unroll
  for (int i4 = 0; i4 < 8; i4++){
    float4 qa0 = ag4[(size_t)n0*8 + i4], qh0 = h4[(size_t)n0*8 + i4];
    float4 qa1 = ag4[(size_t)n1*8 + i4], qh1 = h4[(size_t)n1*8 + i4];
    #pragma unroll
    for (int ii = 0; ii < 4; ii++){
      int i = i4*4 + ii;
      float va0 = (&qa0.x)[ii], vh0 = (&qh0.x)[ii];
      float va1 = (&qa1.x)[ii], vh1 = (&qh1.x)[ii];
      #pragma unroll
      for (int j = 0; j < HID; j++){
        float wr = sWr[i*HID + j], wo = sWo[i*HID + j];
        a0[j] += va0*wr + vh0*wo;
        a1[j] += va1*wr + vh1*wo;
      }
    }
  }
  #pragma unroll
  for (int j = 0; j < HID; j++){ a0[j] += sbr[j]; a1[j] += sbr[j]; }

  // store h1
  float4* h14 = reinterpret_cast<float4*>(g_h1);
  #pragma unroll
  for (int j4 = 0; j4 < 8; j4++){
    h14[(size_t)n0*8 + j4] = make_float4(a0[j4*4],a0[j4*4+1],a0[j4*4+2],a0[j4*4+3]);
    h14[(size_t)n1*8 + j4] = make_float4(a1[j4*4],a1[j4*4+1],a1[j4*4+2],a1[j4*4+3]);
  }

  // pooling logits + softmax (K=16)
  float t0[KC], t1[KC];
  #pragma unroll
  for (int j = 0; j < KC; j++){ t0[j] = sbp[j]; t1[j] = sbp[j]; }
  #pragma unroll
  for (int i = 0; i < HID; i++){
    float v0 = a0[i], v1 = a1[i];
    #pragma unroll
    for (int j = 0; j < KC; j++){
      float w = sWp[i*KC + j];
      t0[j] += v0*w;
      t1[j] += v1*w;
    }
  }
  float m0 = t0[0], m1 = t1[0];
  #pragma unroll
  for (int j = 1; j < KC; j++){ m0 = fmaxf(m0, t0[j]); m1 = fmaxf(m1, t1[j]); }
  float s0 = 0.f, s1 = 0.f;
  #pragma unroll
  for (int j = 0; j < KC; j++){
    t0[j] = expf(t0[j] - m0); s0 += t0[j];
    t1[j] = expf(t1[j] - m1); s1 += t1[j];
  }
  float i0 = 1.f/s0, i1 = 1.f/s1;
  float4* s4 = reinterpret_cast<float4*>(g_s);
  float4* as4 = reinterpret_cast<float4*>(g_as);
  float4 z4 = make_float4(0.f,0.f,0.f,0.f);
  #pragma unroll
  for (int j4 = 0; j4 < 4; j4++){
    s4[(size_t)n0*4 + j4] = make_float4(t0[j4*4]*i0,t0[j4*4+1]*i0,t0[j4*4+2]*i0,t0[j4*4+3]*i0);
    s4[(size_t)n1*4 + j4] = make_float4(t1[j4*4]*i1,t1[j4*4+1]*i1,t1[j4*4+2]*i1,t1[j4*4+3]*i1);
    as4[(size_t)n0*4 + j4] = z4;
    as4[(size_t)n1*4 + j4] = z4;
  }
}

// ---------------- K4: edge scatter: AS[src] += s[dst] ----------------
__global__ void k4(const int* __restrict__ ei){
  int e = blockIdx.x*blockDim.x + threadIdx.x;
  if (e >= NE) return;
  int src = __ldg(ei + e);
  int dst = __ldg(ei + NE + e);
  const float4* sv = reinterpret_cast<const float4*>(g_s) + (size_t)dst*4;
  float* ap = g_as + (size_t)src*KC;
  #pragma unroll
  for (int i = 0; i < 4; i++){
    float4 v = __ldg(sv + i);
    red4(ap + i*4, v.x, v.y, v.z, v.w);
  }
}

// ---------------- K5: per-graph reductions (4 blocks/graph, 256 nodes each) ----------------
__global__ void __launch_bounds__(256) k5(){
  __shared__ float sh_s[64*KC], sh_h[64*HID], sh_a[64*KC], sh_d[64];
  int tid = threadIdx.x;
  int b = blockIdx.x >> 2, sub = blockIdx.x & 3;
  int gbase = b*NPG + sub*256;
  int k = tid >> 4, l = tid & 15;
  float oadj = 0.f, ssv = 0.f, o0 = 0.f, o1 = 0.f, denp = 0.f;

  for (int c = 0; c < 4; c++){
    int nb = gbase + c*64;
    ((float4*)sh_s)[tid] = ((const float4*)(g_s  + (size_t)nb*KC ))[tid];
    ((float4*)sh_a)[tid] = ((const float4*)(g_as + (size_t)nb*KC ))[tid];
    ((float4*)sh_h)[tid]       = ((const float4*)(g_h1 + (size_t)nb*HID))[tid];
    ((float4*)sh_h)[tid + 256] = ((const float4*)(g_h1 + (size_t)nb*HID))[tid + 256];
    if (tid < 64) sh_d[tid] = g_deg[nb + tid];
    __syncthreads();
    #pragma unroll 4
    for (int n = 0; n < 64; n++){
      float sk = sh_s[n*KC + k];
      oadj += sk * sh_a[n*KC + l];
      ssv  += sk * sh_s[n*KC + l];
      o0   += sk * sh_h[n*HID + l];
      o1   += sk * sh_h[n*HID + 16 + l];
      if (l == 0) denp += sh_d[n]*sk*sk;
    }
    __syncthreads();
  }
  atomicAdd(&g_oa[b*256 + tid], oadj);
  atomicAdd(&g_ss[b*256 + tid], ssv);
  atomicAdd(&g_out[b*512 + k*HID + l], o0);
  atomicAdd(&g_out[b*512 + k*HID + 16 + l], o1);
  if (l == 0) atomicAdd(&g_den[b], denp);
}

// ---------------- K6: per-graph finalize (1 warp per graph) ----------------
__global__ void k6(const float* __restrict__ Wrel2, const float* __restrict__ brel2,
                   const float* __restrict__ Wroot2, const float* __restrict__ W2,
                   const float* __restrict__ b2, const float* __restrict__ W3,
                   const float* __restrict__ b3, float* __restrict__ out){
  int b = blockIdx.x, lane = threadIdx.x;
  __shared__ float s_oa[256], s_ss[256], s_out[512], s_d[16], s_c[16],
                   s_u[32], s_v[32], s_g[32], s_z[32];
  for (int u = lane; u < 256; u += 32){ s_oa[u] = g_oa[b*256+u]; s_ss[u] = g_ss[b*256+u]; }
  for (int u = lane; u < 512; u += 32) s_out[u] = g_out[b*512+u];
  __syncwarp();

  float diag = 0.f;
  if (lane < 16){
    diag = s_oa[lane*16 + lane];
    float rs = 0.f;
    #pragma unroll
    for (int l = 0; l < 16; l++) rs += s_oa[lane*16 + l];
    rs -= diag;
    s_d[lane] = sqrtf(fmaxf(rs, 0.f)) + 1e-15f;
    s_oa[lane*16 + lane] = 0.f;
  }
  float num = diag;
  #pragma unroll
  for (int o = 16; o > 0; o >>= 1) num += __shfl_xor_sync(0xffffffffu, num, o);

  float sq = 0.f;
  for (int u = lane; u < 256; u += 32){ float v = s_ss[u]; sq += v*v; }
  #pragma unroll
  for (int o = 16; o > 0; o >>= 1) sq += __shfl_xor_sync(0xffffffffu, sq, o);
  float nrm = sqrtf(sq);
  float osq = 0.f;
  for (int u = lane; u < 256; u += 32){
    float v = s_ss[u]/nrm - (((u >> 4) == (u & 15)) ? 0.25f : 0.f);
    osq += v*v;
  }
  #pragma unroll
  for (int o = 16; o > 0; o >>= 1) osq += __shfl_xor_sync(0xffffffffu, osq, o);
  float den = g_den[b];
  if (lane == 0){
    g_loss[b] = -(num/den);
    g_loss[NB + b] = sqrtf(osq);
  }
  __syncwarp();

  // column sums of normalized adjacency: c[j] = sum_k oa[k][j]/(d[k]*d[j])
  if (lane < 16){
    float c = 0.f;
    #pragma unroll
    for (int kk = 0; kk < 16; kk++) c += s_oa[kk*16 + lane] / s_d[kk];
    s_c[lane] = c / s_d[lane];
  }
  __syncwarp();

  // u = sum_j c[j]*out[j,:], v = sum_j out[j,:]
  {
    float uu = 0.f, vv = 0.f;
    #pragma unroll
    for (int j = 0; j < 16; j++){
      float o = s_out[j*32 + lane];
      uu += s_c[j]*o;
      vv += o;
    }
    s_u[lane] = uu; s_v[lane] = vv;
  }
  __syncwarp();

  float gh = 16.f * brel2[lane];
  #pragma unroll
  for (int i = 0; i < 32; i++)
    gh += s_u[i]*Wrel2[lane*32 + i] + s_v[i]*Wroot2[lane*32 + i];
  s_g[lane] = gh;
  __syncwarp();

  float z = b2[lane];
  #pragma unroll
  for (int i = 0; i < 32; i++) z += s_g[i]*W2[lane*32 + i];
  z = fmaxf(z, 0.f);
  s_z[lane] = z;
  __syncwarp();

  float z2 = -1e30f;
  if (lane < OUTC){
    z2 = b3[lane];
    #pragma unroll
    for (int i = 0; i < 32; i++) z2 += s_z[i]*W3[lane*32 + i];
  }
  float m = z2;
  #pragma unroll
  for (int o = 16; o > 0; o >>= 1) m = fmaxf(m, __shfl_xor_sync(0xffffffffu, m, o));
  float e = (lane < OUTC) ? expf(z2 - m) : 0.f;
  float se = e;
  #pragma unroll
  for (int o = 16; o > 0; o >>= 1) se += __shfl_xor_sync(0xffffffffu, se, o);
  float lse = m + logf(se);
  if (lane < OUTC) out[b*OUTC + lane] = z2 - lse;
}

// ---------------- K7: loss means ----------------
__global__ void k7(float* __restrict__ out){
  int t = threadIdx.x;  // 32
  float m = g_loss[t] + g_loss[t + 32];
  float o = g_loss[NB + t] + g_loss[NB + t + 32];
  #pragma unroll
  for (int s = 16; s > 0; s >>= 1){
    m += __shfl_xor_sync(0xffffffffu, m, s);
    o += __shfl_xor_sync(0xffffffffu, o, s);
  }
  if (t == 0){
    out[NB*OUTC]     = m * (1.f/64.f);
    out[NB*OUTC + 1] = o * (1.f/64.f);
  }
}

// ---------------- launch ----------------
extern "C" void kernel_launch(void* const* d_in, const int* in_sizes, int n_in,
                              void* d_out, int out_size){
  const float* x      = (const float*)d_in[0];
  const float* W1     = (const float*)d_in[1];
  const float* b1     = (const float*)d_in[2];
  const float* Wrel1  = (const float*)d_in[3];
  const float* brel1  = (const float*)d_in[4];
  const float* Wroot1 = (const float*)d_in[5];
  const float* Wp     = (const float*)d_in[6];
  const float* bp     = (const float*)d_in[7];
  const float* Wrel2  = (const float*)d_in[8];
  const float* brel2  = (const float*)d_in[9];
  const float* Wroot2 = (const float*)d_in[10];
  const float* W2     = (const float*)d_in[11];
  const float* b2     = (const float*)d_in[12];
  const float* W3     = (const float*)d_in[13];
  const float* b3     = (const float*)d_in[14];
  const int*   ei     = (const int*)d_in[15];
  float* out = (float*)d_out;

  k1<<<512, 256>>>(x, W1, b1);
  k2<<<NE/256, 256>>>(ei);
  k3<<<128, 256>>>(Wrel1, brel1, Wroot1, Wp, bp);
  k4<<<NE/256, 256>>>(ei);
  k5<<<256, 256>>>();
  k6<<<64, 32>>>(Wrel2, brel2, Wroot2, W2, b2, W3, b3, out);
  k7<<<1, 32>>>(out);
}

// round 2
// speedup vs baseline: 1.1679x; 1.1679x over previous
#include <cuda_runtime.h>
#include <math.h>

#define TOT   65536
#define NB    64
#define NPG   1024
#define NE    2097152
#define INCH  128
#define HID   32
#define KC    16
#define OUTC  10

// ---------------- scratch (static device globals; no allocation) ----------------
__device__ float g_h  [TOT*HID];   // lin1 output
__device__ float g_agg[TOT*HID];   // A @ h
__device__ float g_h1 [TOT*HID];   // conv1 output
__device__ float g_s  [TOT*KC];    // softmax assignments
__device__ float g_as [TOT*KC];    // A @ s
__device__ float g_deg[TOT];       // out-degree per node (float)
__device__ int   g_cnt[TOT];       // degree counts (int)
__device__ int   g_off[TOT];       // CSR row offsets
__device__ int   g_cur[TOT];       // fill cursors
__device__ int   g_csr[NE];        // dst indices grouped by src
__device__ float g_out[NB*KC*HID]; // pooled features S^T H
__device__ float g_oa [NB*KC*KC];  // pooled adjacency S^T A S
__device__ float g_ss [NB*KC*KC];  // S^T S
__device__ float g_den[NB];        // tr(S^T D S)
__device__ float g_loss[2*NB];     // per-graph mincut / ortho

// ---------------- CSR build ----------------
__global__ void kz(){
  int gid = blockIdx.x*256 + threadIdx.x;          // 16384 threads
  reinterpret_cast<int4*>(g_cnt)[gid] = make_int4(0,0,0,0);
}

__global__ void kdeg(const int* __restrict__ ei){
  int e = blockIdx.x*1024 + threadIdx.x;
  atomicAdd(&g_cnt[__ldg(ei + e)], 1);
}

// single block, 1024 threads, 64 nodes each: exclusive scan of counts
__global__ void __launch_bounds__(1024) kscan(){
  int tid = threadIdx.x;
  const int4* c4p = reinterpret_cast<const int4*>(g_cnt);
  int sum = 0;
  #pragma unroll
  for (int i = 0; i < 16; i++){
    int4 c = __ldg(c4p + tid*16 + i);
    sum += c.x + c.y + c.z + c.w;
  }
  int lane = tid & 31, wid = tid >> 5;
  int v = sum;
  #pragma unroll
  for (int o = 1; o < 32; o <<= 1){
    int t = __shfl_up_sync(0xffffffffu, v, o);
    if (lane >= o) v += t;
  }
  __shared__ int wsum[32];
  if (lane == 31) wsum[wid] = v;
  __syncthreads();
  if (wid == 0){
    int w = wsum[lane];
    #pragma unroll
    for (int o = 1; o < 32; o <<= 1){
      int t = __shfl_up_sync(0xffffffffu, w, o);
      if (lane >= o) w += t;
    }
    wsum[lane] = w;
  }
  __syncthreads();
  int run = v - sum + (wid > 0 ? wsum[wid-1] : 0);   // exclusive prefix for this thread
  int4* off4 = reinterpret_cast<int4*>(g_off);
  int4* cur4 = reinterpret_cast<int4*>(g_cur);
  float4* deg4 = reinterpret_cast<float4*>(g_deg);
  #pragma unroll
  for (int i = 0; i < 16; i++){
    int4 c = __ldg(c4p + tid*16 + i);
    int4 o;
    o.x = run; o.y = run + c.x; o.z = o.y + c.y; o.w = o.z + c.z;
    run = o.w + c.w;
    off4[tid*16 + i] = o;
    cur4[tid*16 + i] = o;
    deg4[tid*16 + i] = make_float4((float)c.x,(float)c.y,(float)c.z,(float)c.w);
  }
}

__global__ void kfill(const int* __restrict__ ei){
  int e = blockIdx.x*1024 + threadIdx.x;
  int src = __ldg(ei + e);
  int dst = __ldg(ei + NE + e);
  int pos = atomicAdd(&g_cur[src], 1);
  g_csr[pos] = dst;
}

// ---------------- K1: h = x @ W1^T + b1 ; zero pooled scratch ----------------
__global__ void __launch_bounds__(256) k1(const float* __restrict__ x,
                                          const float* __restrict__ W1,
                                          const float* __restrict__ b1){
  __shared__ float sW[INCH*HID];   // sW[i*32+j] = W1[j*128+i]
  __shared__ float sb[HID];
  int tid = threadIdx.x;
  for (int u = tid; u < INCH*HID; u += 256){
    int i = u >> 5, j = u & 31;
    sW[u] = W1[j*INCH + i];
  }
  if (tid < HID) sb[tid] = b1[tid];

  int gid = blockIdx.x*256 + tid;
  if (gid < NB*KC*HID) g_out[gid] = 0.f;
  if (gid < NB*KC*KC){ g_oa[gid] = 0.f; g_ss[gid] = 0.f; }
  if (gid < NB) g_den[gid] = 0.f;
  __syncthreads();

  int base = blockIdx.x * 128;
  int rg = tid >> 3;           // 0..31 -> 4 rows each
  int cg = tid & 7;            // 0..7  -> 4 cols each
  int r0 = base + rg*4;

  float acc[4][4];
  #pragma unroll
  for (int k = 0; k < 4; k++)
    #pragma unroll
    for (int c = 0; c < 4; c++) acc[k][c] = sb[cg*4 + c];

  #pragma unroll 4
  for (int i4 = 0; i4 < 32; i4++){
    float4 xq[4];
    #pragma unroll
    for (int k = 0; k < 4; k++)
      xq[k] = __ldg(reinterpret_cast<const float4*>(x + (size_t)(r0+k)*INCH) + i4);
    #pragma unroll
    for (int ii = 0; ii < 4; ii++){
      int i = i4*4 + ii;
      float wv[4];
      #pragma unroll
      for (int c = 0; c < 4; c++) wv[c] = sW[i*32 + cg*4 + c];
      #pragma unroll
      for (int k = 0; k < 4; k++){
        float xs = (&xq[k].x)[ii];
        #pragma unroll
        for (int c = 0; c < 4; c++) acc[k][c] += xs * wv[c];
      }
    }
  }
  float4* h4 = reinterpret_cast<float4*>(g_h);
  #pragma unroll
  for (int k = 0; k < 4; k++)
    h4[(size_t)(r0+k)*8 + cg] = make_float4(acc[k][0],acc[k][1],acc[k][2],acc[k][3]);
}

// ---------------- K2p: pull-mode agg[n] = sum over CSR of h[dst] ----------------
// warp per node, lane = channel
__global__ void __launch_bounds__(256) k2p(){
  int wid = threadIdx.x >> 5, lane = threadIdx.x & 31;
  int n = blockIdx.x*8 + wid;
  int start = __ldg(g_off + n), cnt = __ldg(g_cnt + n);
  float acc = 0.f;
  for (int base = 0; base < cnt; base += 32){
    int m = cnt - base; if (m > 32) m = 32;
    int idx = (lane < m) ? __ldg(g_csr + start + base + lane) : 0;
    int i = 0;
    for (; i + 4 <= m; i += 4){
      int d0 = __shfl_sync(0xffffffffu, idx, i);
      int d1 = __shfl_sync(0xffffffffu, idx, i+1);
      int d2 = __shfl_sync(0xffffffffu, idx, i+2);
      int d3 = __shfl_sync(0xffffffffu, idx, i+3);
      float v0 = __ldg(g_h + (size_t)d0*HID + lane);
      float v1 = __ldg(g_h + (size_t)d1*HID + lane);
      float v2 = __ldg(g_h + (size_t)d2*HID + lane);
      float v3 = __ldg(g_h + (size_t)d3*HID + lane);
      acc += (v0 + v1) + (v2 + v3);
    }
    for (; i < m; i++){
      int d = __shfl_sync(0xffffffffu, idx, i);
      acc += __ldg(g_h + (size_t)d*HID + lane);
    }
  }
  g_agg[(size_t)n*HID + lane] = acc;
}

// ---------------- K3: h1 = agg@Wrel1^T + h@Wroot1^T + brel1; s = softmax(h1@Wp^T+bp) ----------------
__global__ void __launch_bounds__(256) k3(const float* __restrict__ Wrel1,
                                          const float* __restrict__ brel1,
                                          const float* __restrict__ Wroot1,
                                          const float* __restrict__ Wp,
                                          const float* __restrict__ bp){
  __shared__ float sWr[HID*HID], sWo[HID*HID], sWp[HID*KC], sbr[HID], sbp[KC];
  int tid = threadIdx.x;
  for (int u = tid; u < HID*HID; u += 256){
    int i = u >> 5, j = u & 31;
    sWr[u] = Wrel1[j*HID + i];
    sWo[u] = Wroot1[j*HID + i];
  }
  for (int u = tid; u < HID*KC; u += 256){
    int i = u >> 4, j = u & 15;
    sWp[u] = Wp[j*HID + i];
  }
  if (tid < HID) sbr[tid] = brel1[tid];
  if (tid < KC)  sbp[tid] = bp[tid];
  __syncthreads();

  int n0 = blockIdx.x*512 + tid;
  int n1 = n0 + 256;

  float a0[HID], a1[HID];
  #pragma unroll
  for (int j = 0; j < HID; j++){ a0[j] = 0.f; a1[j] = 0.f; }

  const float4* ag4 = reinterpret_cast<const float4*>(g_agg);
  const float4* h4  = reinterpret_cast<const float4*>(g_h);
  #pragma unroll
  for (int i4 = 0; i4 < 8; i4++){
    float4 qa0 = ag4[(size_t)n0*8 + i4], qh0 = h4[(size_t)n0*8 + i4];
    float4 qa1 = ag4[(size_t)n1*8 + i4], qh1 = h4[(size_t)n1*8 + i4];
    #pragma unroll
    for (int ii = 0; ii < 4; ii++){
      int i = i4*4 + ii;
      float va0 = (&qa0.x)[ii], vh0 = (&qh0.x)[ii];
      float va1 = (&qa1.x)[ii], vh1 = (&qh1.x)[ii];
      #pragma unroll
      for (int j = 0; j < HID; j++){
        float wr = sWr[i*HID + j], wo = sWo[i*HID + j];
        a0[j] += va0*wr + vh0*wo;
        a1[j] += va1*wr + vh1*wo;
      }
    }
  }
  #pragma unroll
  for (int j = 0; j < HID; j++){ a0[j] += sbr[j]; a1[j] += sbr[j]; }

  float4* h14 = reinterpret_cast<float4*>(g_h1);
  #pragma unroll
  for (int j4 = 0; j4 < 8; j4++){
    h14[(size_t)n0*8 + j4] = make_float4(a0[j4*4],a0[j4*4+1],a0[j4*4+2],a0[j4*4+3]);
    h14[(size_t)n1*8 + j4] = make_float4(a1[j4*4],a1[j4*4+1],a1[j4*4+2],a1[j4*4+3]);
  }

  float t0[KC], t1[KC];
  #pragma unroll
  for (int j = 0; j < KC; j++){ t0[j] = sbp[j]; t1[j] = sbp[j]; }
  #pragma unroll
  for (int i = 0; i < HID; i++){
    float v0 = a0[i], v1 = a1[i];
    #pragma unroll
    for (int j = 0; j < KC; j++){
      float w = sWp[i*KC + j];
      t0[j] += v0*w;
      t1[j] += v1*w;
    }
  }
  float m0 = t0[0], m1 = t1[0];
  #pragma unroll
  for (int j = 1; j < KC; j++){ m0 = fmaxf(m0, t0[j]); m1 = fmaxf(m1, t1[j]); }
  float s0 = 0.f, s1 = 0.f;
  #pragma unroll
  for (int j = 0; j < KC; j++){
    t0[j] = expf(t0[j] - m0); s0 += t0[j];
    t1[j] = expf(t1[j] - m1); s1 += t1[j];
  }
  float i0 = 1.f/s0, i1 = 1.f/s1;
  float4* s4 = reinterpret_cast<float4*>(g_s);
  #pragma unroll
  for (int j4 = 0; j4 < 4; j4++){
    s4[(size_t)n0*4 + j4] = make_float4(t0[j4*4]*i0,t0[j4*4+1]*i0,t0[j4*4+2]*i0,t0[j4*4+3]*i0);
    s4[(size_t)n1*4 + j4] = make_float4(t1[j4*4]*i1,t1[j4*4+1]*i1,t1[j4*4+2]*i1,t1[j4*4+3]*i1);
  }
}

// ---------------- K4p: pull-mode AS[n] = sum over CSR of s[dst] ----------------
// warp per node, 2 edges per iteration (lane = 16*half + channel)
__global__ void __launch_bounds__(256) k4p(){
  int wid = threadIdx.x >> 5, lane = threadIdx.x & 31;
  int c = lane & 15, half = lane >> 4;
  int n = blockIdx.x*8 + wid;
  int start = __ldg(g_off + n), cnt = __ldg(g_cnt + n);
  float acc = 0.f;
  for (int base = 0; base < cnt; base += 32){
    int m = cnt - base; if (m > 32) m = 32;
    int idx = (lane < m) ? __ldg(g_csr + start + base + lane) : 0;
    int i = 0;
    for (; i + 4 <= m; i += 4){
      int d0 = __shfl_sync(0xffffffffu, idx, i + half);
      int d1 = __shfl_sync(0xffffffffu, idx, i + 2 + half);
      float v0 = __ldg(g_s + (size_t)d0*KC + c);
      float v1 = __ldg(g_s + (size_t)d1*KC + c);
      acc += v0 + v1;
    }
    for (; i < m; i += 2){
      int j = i + half;
      int d = __shfl_sync(0xffffffffu, idx, (j < m) ? j : 0);
      if (j < m) acc += __ldg(g_s + (size_t)d*KC + c);
    }
  }
  acc += __shfl_xor_sync(0xffffffffu, acc, 16);
  if (lane < KC) g_as[(size_t)n*KC + lane] = acc;
}

// ---------------- K5: per-graph reductions (4 blocks/graph, 256 nodes each) ----------------
__global__ void __launch_bounds__(256) k5(){
  __shared__ float sh_s[64*KC], sh_h[64*HID], sh_a[64*KC], sh_d[64];
  int tid = threadIdx.x;
  int b = blockIdx.x >> 2, sub = blockIdx.x & 3;
  int gbase = b*NPG + sub*256;
  int k = tid >> 4, l = tid & 15;
  float oadj = 0.f, ssv = 0.f, o0 = 0.f, o1 = 0.f, denp = 0.f;

  for (int c = 0; c < 4; c++){
    int nb = gbase + c*64;
    ((float4*)sh_s)[tid] = ((const float4*)(g_s  + (size_t)nb*KC ))[tid];
    ((float4*)sh_a)[tid] = ((const float4*)(g_as + (size_t)nb*KC ))[tid];
    ((float4*)sh_h)[tid]       = ((const float4*)(g_h1 + (size_t)nb*HID))[tid];
    ((float4*)sh_h)[tid + 256] = ((const float4*)(g_h1 + (size_t)nb*HID))[tid + 256];
    if (tid < 64) sh_d[tid] = g_deg[nb + tid];
    __syncthreads();
    #pragma unroll 4
    for (int n = 0; n < 64; n++){
      float sk = sh_s[n*KC + k];
      oadj += sk * sh_a[n*KC + l];
      ssv  += sk * sh_s[n*KC + l];
      o0   += sk * sh_h[n*HID + l];
      o1   += sk * sh_h[n*HID + 16 + l];
      if (l == 0) denp += sh_d[n]*sk*sk;
    }
    __syncthreads();
  }
  atomicAdd(&g_oa[b*256 + tid], oadj);
  atomicAdd(&g_ss[b*256 + tid], ssv);
  atomicAdd(&g_out[b*512 + k*HID + l], o0);
  atomicAdd(&g_out[b*512 + k*HID + 16 + l], o1);
  if (l == 0) atomicAdd(&g_den[b], denp);
}

// ---------------- K6: per-graph finalize (1 warp per graph) ----------------
__global__ void k6(const float* __restrict__ Wrel2, const float* __restrict__ brel2,
                   const float* __restrict__ Wroot2, const float* __restrict__ W2,
                   const float* __restrict__ b2, const float* __restrict__ W3,
                   const float* __restrict__ b3, float* __restrict__ out){
  int b = blockIdx.x, lane = threadIdx.x;
  __shared__ float s_oa[256], s_ss[256], s_out[512], s_d[16], s_c[16],
                   s_u[32], s_v[32], s_g[32], s_z[32];
  for (int u = lane; u < 256; u += 32){ s_oa[u] = g_oa[b*256+u]; s_ss[u] = g_ss[b*256+u]; }
  for (int u = lane; u < 512; u += 32) s_out[u] = g_out[b*512+u];
  __syncwarp();

  float diag = 0.f;
  if (lane < 16){
    diag = s_oa[lane*16 + lane];
    float rs = 0.f;
    #pragma unroll
    for (int l = 0; l < 16; l++) rs += s_oa[lane*16 + l];
    rs -= diag;
    s_d[lane] = sqrtf(fmaxf(rs, 0.f)) + 1e-15f;
    s_oa[lane*16 + lane] = 0.f;
  }
  float num = diag;
  #pragma unroll
  for (int o = 16; o > 0; o >>= 1) num += __shfl_xor_sync(0xffffffffu, num, o);

  float sq = 0.f;
  for (int u = lane; u < 256; u += 32){ float v = s_ss[u]; sq += v*v; }
  #pragma unroll
  for (int o = 16; o > 0; o >>= 1) sq += __shfl_xor_sync(0xffffffffu, sq, o);
  float nrm = sqrtf(sq);
  float osq = 0.f;
  for (int u = lane; u < 256; u += 32){
    float v = s_ss[u]/nrm - (((u >> 4) == (u & 15)) ? 0.25f : 0.f);
    osq += v*v;
  }
  #pragma unroll
  for (int o = 16; o > 0; o >>= 1) osq += __shfl_xor_sync(0xffffffffu, osq, o);
  float den = g_den[b];
  if (lane == 0){
    g_loss[b] = -(num/den);
    g_loss[NB + b] = sqrtf(osq);
  }
  __syncwarp();

  if (lane < 16){
    float c = 0.f;
    #pragma unroll
    for (int kk = 0; kk < 16; kk++) c += s_oa[kk*16 + lane] / s_d[kk];
    s_c[lane] = c / s_d[lane];
  }
  __syncwarp();

  {
    float uu = 0.f, vv = 0.f;
    #pragma unroll
    for (int j = 0; j < 16; j++){
      float o = s_out[j*32 + lane];
      uu += s_c[j]*o;
      vv += o;
    }
    s_u[lane] = uu; s_v[lane] = vv;
  }
  __syncwarp();

  float gh = 16.f * brel2[lane];
  #pragma unroll
  for (int i = 0; i < 32; i++)
    gh += s_u[i]*Wrel2[lane*32 + i] + s_v[i]*Wroot2[lane*32 + i];
  s_g[lane] = gh;
  __syncwarp();

  float z = b2[lane];
  #pragma unroll
  for (int i = 0; i < 32; i++) z += s_g[i]*W2[lane*32 + i];
  z = fmaxf(z, 0.f);
  s_z[lane] = z;
  __syncwarp();

  float z2 = -1e30f;
  if (lane < OUTC){
    z2 = b3[lane];
    #pragma unroll
    for (int i = 0; i < 32; i++) z2 += s_z[i]*W3[lane*32 + i];
  }
  float m = z2;
  #pragma unroll
  for (int o = 16; o > 0; o >>= 1) m = fmaxf(m, __shfl_xor_sync(0xffffffffu, m, o));
  float e = (lane < OUTC) ? expf(z2 - m) : 0.f;
  float se = e;
  #pragma unroll
  for (int o = 16; o > 0; o >>= 1) se += __shfl_xor_sync(0xffffffffu, se, o);
  float lse = m + logf(se);
  if (lane < OUTC) out[b*OUTC + lane] = z2 - lse;
}

// ---------------- K7: loss means ----------------
__global__ void k7(float* __restrict__ out){
  int t = threadIdx.x;  // 32
  float m = g_loss[t] + g_loss[t + 32];
  float o = g_loss[NB + t] + g_loss[NB + t + 32];
  #pragma unroll
  for (int s = 16; s > 0; s >>= 1){
    m += __shfl_xor_sync(0xffffffffu, m, s);
    o += __shfl_xor_sync(0xffffffffu, o, s);
  }
  if (t == 0){
    out[NB*OUTC]     = m * (1.f/64.f);
    out[NB*OUTC + 1] = o * (1.f/64.f);
  }
}

// ---------------- launch ----------------
extern "C" void kernel_launch(void* const* d_in, const int* in_sizes, int n_in,
                              void* d_out, int out_size){
  const float* x      = (const float*)d_in[0];
  const float* W1     = (const float*)d_in[1];
  const float* b1     = (const float*)d_in[2];
  const float* Wrel1  = (const float*)d_in[3];
  const float* brel1  = (const float*)d_in[4];
  const float* Wroot1 = (const float*)d_in[5];
  const float* Wp     = (const float*)d_in[6];
  const float* bp     = (const float*)d_in[7];
  const float* Wrel2  = (const float*)d_in[8];
  const float* brel2  = (const float*)d_in[9];
  const float* Wroot2 = (const float*)d_in[10];
  const float* W2     = (const float*)d_in[11];
  const float* b2     = (const float*)d_in[12];
  const float* W3     = (const float*)d_in[13];
  const float* b3     = (const float*)d_in[14];
  const int*   ei     = (const int*)d_in[15];
  float* out = (float*)d_out;

  kz   <<<64, 256>>>();
  kdeg <<<NE/1024, 1024>>>(ei);
  kscan<<<1, 1024>>>();
  kfill<<<NE/1024, 1024>>>(ei);
  k1   <<<512, 256>>>(x, W1, b1);
  k2p  <<<TOT/8, 256>>>();
  k3   <<<128, 256>>>(Wrel1, brel1, Wroot1, Wp, bp);
  k4p  <<<TOT/8, 256>>>();
  k5   <<<256, 256>>>();
  k6   <<<64, 32>>>(Wrel2, brel2, Wroot2, W2, b2, W3, b3, out);
  k7   <<<1, 32>>>(out);
}